// round 14
// baseline (speedup 1.0000x reference)
#include <cuda_runtime.h>
#include <cstdint>
#include <cstddef>

// Problem constants
#define BB 2
#define PP 4000
#define NPTS 4096
#define DD 64
#define DSC 64
#define MM 512
#define KK 8
#define NXX 432
#define NYY 496
#define HW (NXX*NYY)        // 214272

#define NSPLIT_PTS 16
#define PTS_PER_SPLIT (NPTS/NSPLIT_PTS)   // 256
#define NSPLIT_MEM 8
#define MEM_PER_SPLIT (MM/NSPLIT_MEM)     // 64
#define TILE_P 128                        // pillars per block
#define TILE_R 32                         // B rows per tile
#define ASTR 130                          // A_s row stride in float2 (16B-aligned rows)
#define BSTR 34                           // B_s row stride in float2
#define PTS_SLOTS (NSPLIT_PTS*2*KK)       // 256 (x2 for row-halves)
#define MEM_SLOTS (NSPLIT_MEM*2*KK)       // 128
#define SLOT_STRIDE (PTS_SLOTS+MEM_SLOTS) // 384 per pillar
#define BPP (BB*PP)                       // 8000

// ---- device scratch (no allocations allowed; 16B-aligned) ----
__device__ __align__(16) int   g_winner[BB*HW];
__device__ __align__(16) float g_topv[(size_t)BPP*SLOT_STRIDE];   // [g][slot]
__device__ __align__(16) int   g_topi[(size_t)BPP*SLOT_STRIDE];

// ---- packed fp32x2 helpers (Blackwell paired-FP32 pipe) ----
typedef unsigned long long u64t;
__device__ __forceinline__ void up2(u64t a, float& x, float& y) {
    asm("mov.b64 {%0, %1}, %2;" : "=f"(x), "=f"(y) : "l"(a));
}
__device__ __forceinline__ void fma2(u64t& d, u64t a, u64t b) {
    asm("fma.rn.f32x2 %0, %1, %2, %0;" : "+l"(d) : "l"(a), "l"(b));
}
__device__ __forceinline__ float hadd2(u64t a) {
    float x, y; up2(a, x, y); return x + y;
}

// ---- register-resident top-8 insertion ----
__device__ __forceinline__ void ins8(float v, int id, float tv[KK], int ti[KK],
                                     float& vmin, int& pmin) {
    if (v > vmin) {
#pragma unroll
        for (int k = 0; k < KK; k++) if (k == pmin) { tv[k] = v; ti[k] = id; }
        vmin = tv[0]; pmin = 0;
#pragma unroll
        for (int k = 1; k < KK; k++) if (tv[k] < vmin) { vmin = tv[k]; pmin = k; }
    }
}

// ============================================================================
// GEMM-tiled top-k: block = 128 pillars x 32-row B-tiles, both operands in
// smem. Thread = 2 adjacent pillars x 16 rows (its half of each tile); topk
// state for both pillars lives in registers (no staging). Row-halves are
// disjoint -> 2x candidate slots, merged later.
//   blockIdx.y <  NSPLIT_PTS          : points split (256 rows = 8 tiles)
//   blockIdx.y >= NSPLIT_PTS (8 more) : memory split  (64 rows = 2 tiles)
// ============================================================================
__global__ void __launch_bounds__(128, 5)
k_topk_all(const float* __restrict__ pillars,
           const float* __restrict__ points,
           const float* __restrict__ W)
{
    const int b    = blockIdx.z;
    const int y    = blockIdx.y;
    const int tid  = threadIdx.x;
    const int pair = tid & 63;        // pillar pair id (0..63)
    const int half = tid >> 6;        // row half (0..1)
    const int pbase = blockIdx.x * TILE_P;
    const int p0 = pbase + pair * 2;
    const int p1 = p0 + 1;

    const float* rsrc;
    int base, ntiles, slotBase;
    if (y < NSPLIT_PTS) {
        rsrc = points + (size_t)b * NPTS * DD;
        base = y * PTS_PER_SPLIT; ntiles = PTS_PER_SPLIT / TILE_R;
        slotBase = (y * 2 + half) * KK;
    } else {
        rsrc = W;
        base = (y - NSPLIT_PTS) * MEM_PER_SPLIT; ntiles = MEM_PER_SPLIT / TILE_R;
        slotBase = PTS_SLOTS + ((y - NSPLIT_PTS) * 2 + half) * KK;
    }

    __shared__ __align__(16) float2 A_s[32 * ASTR];   // [d2][pillar]
    __shared__ __align__(16) float2 B_s[32 * BSTR];   // [d2][row]

    // A-tile load (once): 128 pillars x 32 float2, transposed to [d2][pillar].
    // Gmem coalesced (warp reads 32 consecutive float2 of one pillar row).
    for (int i = tid; i < TILE_P * 32; i += 128) {
        const int pi = i >> 5, d2 = i & 31;
        const int prow = min(pbase + pi, PP - 1);
        A_s[d2 * ASTR + pi] =
            ((const float2*)(pillars + ((size_t)b * PP + prow) * DD))[d2];
    }

    float tv0[KK], tv1[KK]; int ti0[KK], ti1[KK];
#pragma unroll
    for (int k = 0; k < KK; k++) {
        tv0[k] = -3.0e38f; ti0[k] = 0; tv1[k] = -3.0e38f; ti1[k] = 0;
    }
    float vmin0 = -3.0e38f, vmin1 = -3.0e38f; int pmin0 = 0, pmin1 = 0;

    for (int t = 0; t < ntiles; t++) {
        const int tb = base + t * TILE_R;
        // B-tile load: 32 rows x 32 float2, transposed to [d2][row].
        for (int i = tid; i < TILE_R * 32; i += 128) {
            const int r = i >> 5, d2 = i & 31;
            B_s[d2 * BSTR + r] =
                ((const float2*)(rsrc + (size_t)(tb + r) * DD))[d2];
        }
        __syncthreads();   // covers A_s (first iter) and this B tile

        const float2* Ap = &A_s[pair * 2];
        const float2* Bh = &B_s[half * 16];
#pragma unroll
        for (int rg = 0; rg < 4; rg++) {
            const int r0 = rg * 4;
            u64t ac0[4], ac1[4];
#pragma unroll
            for (int i = 0; i < 4; i++) { ac0[i] = 0; ac1[i] = 0; }
            const float2* Bp = Bh + r0;
#pragma unroll
            for (int d2 = 0; d2 < 32; d2++) {
                const ulonglong2 a  = *(const ulonglong2*)(Ap + d2 * ASTR);
                const ulonglong2 b0 = *(const ulonglong2*)(Bp + d2 * BSTR);
                const ulonglong2 b1 = *(const ulonglong2*)(Bp + d2 * BSTR + 2);
                fma2(ac0[0], a.x, b0.x); fma2(ac0[1], a.x, b0.y);
                fma2(ac0[2], a.x, b1.x); fma2(ac0[3], a.x, b1.y);
                fma2(ac1[0], a.y, b0.x); fma2(ac1[1], a.y, b0.y);
                fma2(ac1[2], a.y, b1.x); fma2(ac1[3], a.y, b1.y);
            }
            const int rid = tb + half * 16 + r0;
#pragma unroll
            for (int i = 0; i < 4; i++) {
                ins8(hadd2(ac0[i]), rid + i, tv0, ti0, vmin0, pmin0);
                ins8(hadd2(ac1[i]), rid + i, tv1, ti1, vmin1, pmin1);
            }
        }
        __syncthreads();
    }

    if (p0 < PP) {
        const size_t o = (size_t)(b * PP + p0) * SLOT_STRIDE + slotBase;
#pragma unroll
        for (int k = 0; k < KK; k++) { g_topv[o + k] = tv0[k]; g_topi[o + k] = ti0[k]; }
    }
    if (p1 < PP) {
        const size_t o = (size_t)(b * PP + p1) * SLOT_STRIDE + slotBase;
#pragma unroll
        for (int k = 0; k < KK; k++) { g_topv[o + k] = tv1[k]; g_topi[o + k] = ti1[k]; }
    }
}

// ============================================================================
// Warp-per-task merge: 16000 warps; now 256 pts / 128 mem candidate slots.
// ============================================================================
__global__ void __launch_bounds__(256)
k_merge_warp(const float* __restrict__ points, const float* __restrict__ W,
             float* __restrict__ out4, float* __restrict__ out5)
{
    const int wid  = blockIdx.x * 8 + (threadIdx.x >> 5);
    if (wid >= 2 * BPP) return;
    const int lane = threadIdx.x & 31;
    const int g    = wid >> 1;
    const bool isMem = (wid & 1);
    const int b = g / PP;

    const float* rsrc = isMem ? W : points + (size_t)b * NPTS * DD;
    const int base = isMem ? PTS_SLOTS : 0;
    const int nc   = isMem ? (MEM_SLOTS / 32) : (PTS_SLOTS / 32);   // 4 or 8
    float* dst = (isMem ? out5 : out4) + (size_t)g * DD;

    const size_t o = (size_t)g * SLOT_STRIDE + base;
    float cv[8]; int ci[8];
#pragma unroll
    for (int j = 0; j < 8; j++) {
        if (j < nc) { cv[j] = g_topv[o + j*32 + lane]; ci[j] = g_topi[o + j*32 + lane]; }
        else        { cv[j] = -3.0e38f; ci[j] = 0x7FFFFFFF; }
    }

    float tvk[KK]; int tik[KK];
#pragma unroll
    for (int k = 0; k < KK; k++) {
        float bv = cv[0]; int bi = ci[0];
#pragma unroll
        for (int j = 1; j < 8; j++)
            if (cv[j] > bv || (cv[j] == bv && ci[j] < bi)) { bv = cv[j]; bi = ci[j]; }
#pragma unroll
        for (int off = 16; off; off >>= 1) {
            float ov = __shfl_xor_sync(0xFFFFFFFFu, bv, off);
            int   oi = __shfl_xor_sync(0xFFFFFFFFu, bi, off);
            if (ov > bv || (ov == bv && oi < bi)) { bv = ov; bi = oi; }
        }
        tvk[k] = bv; tik[k] = bi;
#pragma unroll
        for (int j = 0; j < 8; j++)
            if (ci[j] == bi) cv[j] = -3.0e38f;
    }

    const float m = tvk[0];
    float w[KK]; float ssum = 0.0f;
#pragma unroll
    for (int k = 0; k < KK; k++) { w[k] = expf(tvk[k] - m); ssum += w[k]; }
    const float inv = 1.0f / ssum;

    float ax = 0.f, ay = 0.f;
#pragma unroll
    for (int k = 0; k < KK; k++) {
        const float wk = w[k] * inv;
        const float2 r = *(const float2*)&rsrc[(size_t)tik[k] * DD + 2*lane];
        ax += wk * r.x; ay += wk * r.y;
    }
    *(float2*)&dst[2*lane] = make_float2(ax, ay);
}

// ============================================================================
// Winner pass (last-wins scatter semantics: max pillar index per cell)
// ============================================================================
__global__ void k_winner_init() {
    int i = blockIdx.x * 256 + threadIdx.x;
    if (i < BB * HW) g_winner[i] = -1;
}

__global__ void k_winner_mark(const int* __restrict__ idx) {
    int g = blockIdx.x * 256 + threadIdx.x;
    if (g >= BPP) return;
    int b = g / PP;
    atomicMax(&g_winner[b * HW + idx[g]], g - b * PP);
}

// ============================================================================
// Fill (proven R11 structure): static planes overlap the compute-bound topk;
// dyn planes run after merge.
// ============================================================================

// 192 planes: t<64 grid1/pillars, t<128 grid2/pillars, else grid3/scale
__global__ void __launch_bounds__(256)
k_fill_static(const float* __restrict__ pillars, const float* __restrict__ scale,
              float* __restrict__ out)
{
    const int b = blockIdx.z;
    const int hw = (blockIdx.x * 256 + threadIdx.x) * 4;
    if (hw >= HW) return;

    const int4 w = *(const int4*)&g_winner[b * HW + hw];
    const bool any = (max(max(w.x, w.y), max(w.z, w.w)) >= 0);
    const size_t G1 = (size_t)BB * 128 * HW;

    const int t0 = blockIdx.y * 32;
#pragma unroll 4
    for (int t = t0; t < t0 + 32; t++) {
        const float* A; int cc; size_t ob;
        if (t < 64)       { A = pillars; cc = t;       ob = ((size_t)b*128 + t) * HW; }
        else if (t < 128) { A = pillars; cc = t - 64;  ob = G1 + ((size_t)b*128 + (t-64)) * HW; }
        else              { A = scale;   cc = t - 128; ob = 2*G1 + ((size_t)b*64 + (t-128)) * HW; }

        float4 v = make_float4(0.f, 0.f, 0.f, 0.f);
        if (any) {
            const float* Ab = A + (size_t)b * PP * 64 + cc;
            if (w.x >= 0) v.x = Ab[(size_t)w.x * 64];
            if (w.y >= 0) v.y = Ab[(size_t)w.y * 64];
            if (w.z >= 0) v.z = Ab[(size_t)w.z * 64];
            if (w.w >= 0) v.w = Ab[(size_t)w.w * 64];
        }
        *(float4*)(out + ob + hw) = v;
    }
}

// 128 planes: t<64 grid1/pos_mem (ch 64+t), else grid2/pos_point (ch 64+(t-64))
__global__ void __launch_bounds__(256)
k_fill_dyn(const float* __restrict__ pos_point, const float* __restrict__ pos_mem,
           float* __restrict__ out)
{
    const int b = blockIdx.z;
    const int hw = (blockIdx.x * 256 + threadIdx.x) * 4;
    if (hw >= HW) return;

    const int4 w = *(const int4*)&g_winner[b * HW + hw];
    const bool any = (max(max(w.x, w.y), max(w.z, w.w)) >= 0);
    const size_t G1 = (size_t)BB * 128 * HW;

    const int t0 = blockIdx.y * 32;
#pragma unroll 4
    for (int t = t0; t < t0 + 32; t++) {
        const float* A; int cc; size_t ob;
        if (t < 64) { A = pos_mem;   cc = t;      ob = ((size_t)b*128 + 64 + t) * HW; }
        else        { A = pos_point; cc = t - 64; ob = G1 + ((size_t)b*128 + 64 + (t-64)) * HW; }

        float4 v = make_float4(0.f, 0.f, 0.f, 0.f);
        if (any) {
            const float* Ab = A + (size_t)b * PP * 64 + cc;
            if (w.x >= 0) v.x = Ab[(size_t)w.x * 64];
            if (w.y >= 0) v.y = Ab[(size_t)w.y * 64];
            if (w.z >= 0) v.z = Ab[(size_t)w.z * 64];
            if (w.w >= 0) v.w = Ab[(size_t)w.w * 64];
        }
        *(float4*)(out + ob + hw) = v;
    }
}

// ============================================================================
// kernel_launch — graph-capturable, allocation-free, two-stream fork/join.
// DAG:  s0: [fork e0] topk ── merge ── [e2] ─────────────── [wait e3]
//       s1: [wait e0] winner_init ── winner_mark ── fill_static ── [wait e2]
//           ── fill_dyn ── [e3]
// ============================================================================
extern "C" void kernel_launch(void* const* d_in, const int* in_sizes, int n_in,
                              void* d_out, int out_size)
{
    const float* pillars = (const float*)d_in[0];
    const float* scale   = (const float*)d_in[1];
    const float* points  = (const float*)d_in[2];
    const float* W       = (const float*)d_in[3];
    const int*   idx     = (const int*)  d_in[4];
    float* out = (float*)d_out;

    const size_t sz12  = (size_t)BB * 128 * HW;
    const size_t sz3   = (size_t)BB * 64 * HW;
    const size_t grids = 2 * sz12 + sz3;
    float* out4 = out + grids;                   // point_positive [B*P, 64]
    float* out5 = out4 + (size_t)BPP * DD;       // memory_positive [B*P, 64]

    // one-time host-side resources (no device memory; identical work per call)
    static cudaStream_t s1 = nullptr;
    static cudaEvent_t e0, e2, e3;
    if (!s1) {
        cudaStreamCreateWithFlags(&s1, cudaStreamNonBlocking);
        cudaEventCreateWithFlags(&e0, cudaEventDisableTiming);
        cudaEventCreateWithFlags(&e2, cudaEventDisableTiming);
        cudaEventCreateWithFlags(&e3, cudaEventDisableTiming);
    }

    // fork s1 from the origin stream
    cudaEventRecord(e0, 0);
    cudaStreamWaitEvent(s1, e0, 0);

    // s1: winner resolution + input-only dense fill (329 MB, DRAM-bound)
    k_winner_init<<<(BB * HW + 255) / 256, 256, 0, s1>>>();
    k_winner_mark<<<(BPP + 255) / 256, 256, 0, s1>>>(idx);
    k_fill_static<<<dim3((HW / 4 + 255) / 256, 6, BB), 256, 0, s1>>>(
        pillars, scale, out);

    // s0: GEMM-tiled topk (1536 blocks, 5/SM), then merge
    k_topk_all<<<dim3((PP + TILE_P - 1) / TILE_P, NSPLIT_PTS + NSPLIT_MEM, BB),
                 128>>>(pillars, points, W);
    k_merge_warp<<<(2 * BPP + 7) / 8, 256>>>(points, W, out4, out5);
    cudaEventRecord(e2, 0);

    // s1: merge-dependent fill (219 MB) after merge completes
    cudaStreamWaitEvent(s1, e2, 0);
    k_fill_dyn<<<dim3((HW / 4 + 255) / 256, 4, BB), 256, 0, s1>>>(
        out4, out5, out);
    cudaEventRecord(e3, s1);

    // join back to origin stream
    cudaStreamWaitEvent(0, e3, 0);
}

// round 15
// speedup vs baseline: 3.9405x; 3.9405x over previous
#include <cuda_runtime.h>
#include <cstdint>
#include <cstddef>

// Problem constants
#define BB 2
#define PP 4000
#define NPTS 4096
#define DD 64
#define DSC 64
#define MM 512
#define KK 8
#define NXX 432
#define NYY 496
#define HW (NXX*NYY)        // 214272

#define NSPLIT_PTS 16
#define PTS_PER_SPLIT (NPTS/NSPLIT_PTS)   // 256
#define NSPLIT_MEM 8
#define MEM_PER_SPLIT (MM/NSPLIT_MEM)     // 64
#define TILE_J 64
#define PTS_SLOTS (NSPLIT_PTS*KK)         // 128
#define MEM_SLOTS (NSPLIT_MEM*KK)         // 64
#define SLOT_STRIDE (PTS_SLOTS+MEM_SLOTS) // 192 per pillar
#define BPP (BB*PP)                       // 8000

// ---- device scratch (no allocations allowed; 16B-aligned) ----
__device__ __align__(16) int   g_winner[BB*HW];
__device__ __align__(16) float g_topv[(size_t)BPP*SLOT_STRIDE];   // [g][slot]
__device__ __align__(16) int   g_topi[(size_t)BPP*SLOT_STRIDE];

// ---- packed fp32x2 helpers (Blackwell paired-FP32 pipe) ----
typedef unsigned long long u64t;
__device__ __forceinline__ u64t pk2(float x, float y) {
    u64t r; asm("mov.b64 %0, {%1, %2};" : "=l"(r) : "f"(x), "f"(y)); return r;
}
__device__ __forceinline__ void up2(u64t a, float& x, float& y) {
    asm("mov.b64 {%0, %1}, %2;" : "=f"(x), "=f"(y) : "l"(a));
}
__device__ __forceinline__ void fma2(u64t& d, u64t a, u64t b) {
    asm("fma.rn.f32x2 %0, %1, %2, %0;" : "+l"(d) : "l"(a), "l"(b));
}

// ---- register-resident top-8 insertion ----
__device__ __forceinline__ void ins8(float v, int id, float tv[KK], int ti[KK],
                                     float& vmin, int& pmin) {
    if (v > vmin) {
#pragma unroll
        for (int k = 0; k < KK; k++) if (k == pmin) { tv[k] = v; ti[k] = id; }
        vmin = tv[0]; pmin = 0;
#pragma unroll
        for (int k = 1; k < KK; k++) if (tv[k] < vmin) { vmin = tv[k]; pmin = k; }
    }
}

// ============================================================================
// Top-k kernel (proven R6/R11 body, unchanged math). yOff selects the split
// range so mem splits (yOff=NSPLIT_PTS, gridDim.y=8) and pts splits (yOff=0,
// gridDim.y=16) can be launched separately for pipelining.
// ============================================================================
__global__ void __launch_bounds__(128)
k_topk(const float* __restrict__ pillars,
       const float* __restrict__ points,
       const float* __restrict__ W, int yOff)
{
    const int b = blockIdx.z;
    const int y = blockIdx.y + yOff;
    const int p = blockIdx.x * 128 + threadIdx.x;
    const bool active = (p < PP);

    const float* rsrc;
    int base, perSplit, slotBase;
    if (y < NSPLIT_PTS) {
        rsrc = points + (size_t)b * NPTS * DD;
        base = y * PTS_PER_SPLIT; perSplit = PTS_PER_SPLIT; slotBase = y * KK;
    } else {
        rsrc = W;
        base = (y - NSPLIT_PTS) * MEM_PER_SPLIT; perSplit = MEM_PER_SPLIT;
        slotBase = PTS_SLOTS + (y - NSPLIT_PTS) * KK;
    }

    __shared__ __align__(16) float spt[TILE_J * DD];

    u64t pr[32];
    if (active) {
        const float4* prow = (const float4*)(pillars + ((size_t)b * PP + p) * DD);
#pragma unroll
        for (int q = 0; q < 16; q++) {
            float4 v = prow[q];
            pr[2*q]   = pk2(v.x, v.y);
            pr[2*q+1] = pk2(v.z, v.w);
        }
    }

    float tv[KK]; int ti[KK];
#pragma unroll
    for (int k = 0; k < KK; k++) { tv[k] = -3.0e38f; ti[k] = 0; }
    float vmin = -3.0e38f; int pmin = 0;

    const int ntiles = perSplit / TILE_J;
    for (int t = 0; t < ntiles; t++) {
        const int tb = base + t * TILE_J;
        const float4* gsrc = (const float4*)(rsrc + (size_t)tb * DD);
#pragma unroll
        for (int r = 0; r < 8; r++)
            ((float4*)spt)[r * 128 + threadIdx.x] = gsrc[r * 128 + threadIdx.x];
        __syncthreads();

        if (active) {
            for (int j = 0; j < TILE_J; j += 4) {
                u64t a0e=0,a0o=0,a1e=0,a1o=0,a2e=0,a2o=0,a3e=0,a3o=0;
                const ulonglong2* r0 = (const ulonglong2*)&spt[(j+0)*DD];
                const ulonglong2* r1 = (const ulonglong2*)&spt[(j+1)*DD];
                const ulonglong2* r2 = (const ulonglong2*)&spt[(j+2)*DD];
                const ulonglong2* r3 = (const ulonglong2*)&spt[(j+3)*DD];
#pragma unroll
                for (int q = 0; q < 16; q++) {
                    ulonglong2 x0 = r0[q], x1 = r1[q], x2 = r2[q], x3 = r3[q];
                    fma2(a0e, pr[2*q], x0.x); fma2(a0o, pr[2*q+1], x0.y);
                    fma2(a1e, pr[2*q], x1.x); fma2(a1o, pr[2*q+1], x1.y);
                    fma2(a2e, pr[2*q], x2.x); fma2(a2o, pr[2*q+1], x2.y);
                    fma2(a3e, pr[2*q], x3.x); fma2(a3o, pr[2*q+1], x3.y);
                }
                float xa, xb, ya, yb, v;
                up2(a0e, xa, xb); up2(a0o, ya, yb); v = (xa + ya) + (xb + yb);
                ins8(v, tb + j + 0, tv, ti, vmin, pmin);
                up2(a1e, xa, xb); up2(a1o, ya, yb); v = (xa + ya) + (xb + yb);
                ins8(v, tb + j + 1, tv, ti, vmin, pmin);
                up2(a2e, xa, xb); up2(a2o, ya, yb); v = (xa + ya) + (xb + yb);
                ins8(v, tb + j + 2, tv, ti, vmin, pmin);
                up2(a3e, xa, xb); up2(a3o, ya, yb); v = (xa + ya) + (xb + yb);
                ins8(v, tb + j + 3, tv, ti, vmin, pmin);
            }
        }
        __syncthreads();
    }

    if (active) {
        const size_t o = (size_t)(b * PP + p) * SLOT_STRIDE + slotBase;
#pragma unroll
        for (int k = 0; k < KK; k++) { g_topv[o + k] = tv[k]; g_topi[o + k] = ti[k]; }
    }
}

// ============================================================================
// Warp-per-task merge (proven R6 body); isMem selects attention type so the
// mem merge can run early. 8000 warps per launch.
// ============================================================================
__global__ void __launch_bounds__(256)
k_merge(const float* __restrict__ points, const float* __restrict__ W,
        float* __restrict__ dstBase, int isMem)
{
    const int g = blockIdx.x * 8 + (threadIdx.x >> 5);
    if (g >= BPP) return;
    const int lane = threadIdx.x & 31;
    const int b = g / PP;

    const float* rsrc = isMem ? W : points + (size_t)b * NPTS * DD;
    const int base = isMem ? PTS_SLOTS : 0;
    const int nc   = isMem ? (MEM_SLOTS / 32) : (PTS_SLOTS / 32);   // 2 or 4
    float* dst = dstBase + (size_t)g * DD;

    const size_t o = (size_t)g * SLOT_STRIDE + base;
    float cv[4]; int ci[4];
#pragma unroll
    for (int j = 0; j < 4; j++) {
        if (j < nc) { cv[j] = g_topv[o + j*32 + lane]; ci[j] = g_topi[o + j*32 + lane]; }
        else        { cv[j] = -3.0e38f; ci[j] = 0x7FFFFFFF; }
    }

    float tvk[KK]; int tik[KK];
#pragma unroll
    for (int k = 0; k < KK; k++) {
        float bv = cv[0]; int bi = ci[0];
#pragma unroll
        for (int j = 1; j < 4; j++)
            if (cv[j] > bv || (cv[j] == bv && ci[j] < bi)) { bv = cv[j]; bi = ci[j]; }
#pragma unroll
        for (int off = 16; off; off >>= 1) {
            float ov = __shfl_xor_sync(0xFFFFFFFFu, bv, off);
            int   oi = __shfl_xor_sync(0xFFFFFFFFu, bi, off);
            if (ov > bv || (ov == bv && oi < bi)) { bv = ov; bi = oi; }
        }
        tvk[k] = bv; tik[k] = bi;
#pragma unroll
        for (int j = 0; j < 4; j++)
            if (ci[j] == bi) cv[j] = -3.0e38f;
    }

    const float m = tvk[0];
    float w[KK]; float ssum = 0.0f;
#pragma unroll
    for (int k = 0; k < KK; k++) { w[k] = expf(tvk[k] - m); ssum += w[k]; }
    const float inv = 1.0f / ssum;

    float ax = 0.f, ay = 0.f;
#pragma unroll
    for (int k = 0; k < KK; k++) {
        const float wk = w[k] * inv;
        const float2 r = *(const float2*)&rsrc[(size_t)tik[k] * DD + 2*lane];
        ax += wk * r.x; ay += wk * r.y;
    }
    *(float2*)&dst[2*lane] = make_float2(ax, ay);
}

// ============================================================================
// Winner pass (last-wins scatter semantics: max pillar index per cell)
// ============================================================================
__global__ void k_winner_init() {
    int i = blockIdx.x * 256 + threadIdx.x;
    if (i < BB * HW) g_winner[i] = -1;
}

__global__ void k_winner_mark(const int* __restrict__ idx) {
    int g = blockIdx.x * 256 + threadIdx.x;
    if (g >= BPP) return;
    int b = g / PP;
    atomicMax(&g_winner[b * HW + idx[g]], g - b * PP);
}

// ============================================================================
// fill_A: 256 planes that need only winner + pos_mem (ready after merge_mem):
//   t in [0,64)    grid1 pillars  ch t
//   t in [64,128)  grid1 pos_mem  ch 64+(t-64)
//   t in [128,192) grid2 pillars  ch (t-128)
//   t in [192,256) grid3 scale    ch (t-192)
// Runs concurrently with the big points topk (439 MB of the 548 MB total).
// ============================================================================
__global__ void __launch_bounds__(256)
k_fill_A(const float* __restrict__ pillars, const float* __restrict__ scale,
         const float* __restrict__ pos_mem, float* __restrict__ out)
{
    const int b = blockIdx.z;
    const int hw = (blockIdx.x * 256 + threadIdx.x) * 4;
    if (hw >= HW) return;

    const int4 w = *(const int4*)&g_winner[b * HW + hw];
    const bool any = (max(max(w.x, w.y), max(w.z, w.w)) >= 0);
    const size_t G1 = (size_t)BB * 128 * HW;

    const int t0 = blockIdx.y * 32;
#pragma unroll 4
    for (int t = t0; t < t0 + 32; t++) {
        const float* A; int cc; size_t ob;
        if (t < 64)       { A = pillars; cc = t;       ob = ((size_t)b*128 + t) * HW; }
        else if (t < 128) { A = pos_mem; cc = t - 64;  ob = ((size_t)b*128 + t) * HW; }
        else if (t < 192) { A = pillars; cc = t - 128; ob = G1 + ((size_t)b*128 + (t-128)) * HW; }
        else              { A = scale;   cc = t - 192; ob = 2*G1 + ((size_t)b*64 + (t-192)) * HW; }

        float4 v = make_float4(0.f, 0.f, 0.f, 0.f);
        if (any) {
            const float* Ab = A + (size_t)b * PP * 64 + cc;
            if (w.x >= 0) v.x = Ab[(size_t)w.x * 64];
            if (w.y >= 0) v.y = Ab[(size_t)w.y * 64];
            if (w.z >= 0) v.z = Ab[(size_t)w.z * 64];
            if (w.w >= 0) v.w = Ab[(size_t)w.w * 64];
        }
        *(float4*)(out + ob + hw) = v;
    }
}

// ============================================================================
// fill_B: 64 planes needing pos_point (after merge_pts): grid2 ch 64+t.
// Only 110 MB exposed on the critical-path tail.
// ============================================================================
__global__ void __launch_bounds__(256)
k_fill_B(const float* __restrict__ pos_point, float* __restrict__ out)
{
    const int b = blockIdx.z;
    const int hw = (blockIdx.x * 256 + threadIdx.x) * 4;
    if (hw >= HW) return;

    const int4 w = *(const int4*)&g_winner[b * HW + hw];
    const bool any = (max(max(w.x, w.y), max(w.z, w.w)) >= 0);
    const size_t G1 = (size_t)BB * 128 * HW;

    const int t0 = blockIdx.y * 32;
#pragma unroll 4
    for (int t = t0; t < t0 + 32; t++) {
        const size_t ob = G1 + ((size_t)b*128 + 64 + t) * HW;
        float4 v = make_float4(0.f, 0.f, 0.f, 0.f);
        if (any) {
            const float* Ab = pos_point + (size_t)b * PP * 64 + t;
            if (w.x >= 0) v.x = Ab[(size_t)w.x * 64];
            if (w.y >= 0) v.y = Ab[(size_t)w.y * 64];
            if (w.z >= 0) v.z = Ab[(size_t)w.z * 64];
            if (w.w >= 0) v.w = Ab[(size_t)w.w * 64];
        }
        *(float4*)(out + ob + hw) = v;
    }
}

// ============================================================================
// kernel_launch — graph-capturable, allocation-free, pipelined fork/join.
// s0: topk_mem ── merge_mem ──[e_m]── topk_pts ── merge_pts ──[e_p]──[wait e3]
// s1: [wait e0] winner ──[wait e_m]── fill_A(439MB, under topk_pts)
//     ──[wait e_p]── fill_B(110MB) ──[e3]
// topk_mem is queued FIRST so compute owns the SMs; fill drains into gaps
// (R12 lesson: overlap is a queue-order property).
// ============================================================================
extern "C" void kernel_launch(void* const* d_in, const int* in_sizes, int n_in,
                              void* d_out, int out_size)
{
    const float* pillars = (const float*)d_in[0];
    const float* scale   = (const float*)d_in[1];
    const float* points  = (const float*)d_in[2];
    const float* W       = (const float*)d_in[3];
    const int*   idx     = (const int*)  d_in[4];
    float* out = (float*)d_out;

    const size_t sz12  = (size_t)BB * 128 * HW;
    const size_t sz3   = (size_t)BB * 64 * HW;
    const size_t grids = 2 * sz12 + sz3;
    float* out4 = out + grids;                   // point_positive [B*P, 64]
    float* out5 = out4 + (size_t)BPP * DD;       // memory_positive [B*P, 64]

    // one-time host-side resources (no device memory; identical work per call)
    static cudaStream_t s1 = nullptr;
    static cudaEvent_t e0, em, ep, e3;
    if (!s1) {
        cudaStreamCreateWithFlags(&s1, cudaStreamNonBlocking);
        cudaEventCreateWithFlags(&e0, cudaEventDisableTiming);
        cudaEventCreateWithFlags(&em, cudaEventDisableTiming);
        cudaEventCreateWithFlags(&ep, cudaEventDisableTiming);
        cudaEventCreateWithFlags(&e3, cudaEventDisableTiming);
    }

    cudaEventRecord(e0, 0);
    cudaStreamWaitEvent(s1, e0, 0);

    // s0: memory-attention topk first (small), so pos_mem is ready early
    k_topk<<<dim3((PP + 127) / 128, NSPLIT_MEM, BB), 128>>>(
        pillars, points, W, NSPLIT_PTS);

    // s1: winner resolution (tiny; fills scheduling gaps)
    k_winner_init<<<(BB * HW + 255) / 256, 256, 0, s1>>>();
    k_winner_mark<<<(BPP + 255) / 256, 256, 0, s1>>>(idx);

    // s0: merge_mem -> pos_mem ready
    k_merge<<<(BPP + 7) / 8, 256>>>(points, W, out5, 1);
    cudaEventRecord(em, 0);

    // s0: the big points topk + merge_pts
    k_topk<<<dim3((PP + 127) / 128, NSPLIT_PTS, BB), 128>>>(
        pillars, points, W, 0);
    k_merge<<<(BPP + 7) / 8, 256>>>(points, W, out4, 0);
    cudaEventRecord(ep, 0);

    // s1: 439 MB of fill that only needs winner + pos_mem (under topk_pts)
    cudaStreamWaitEvent(s1, em, 0);
    k_fill_A<<<dim3((HW / 4 + 255) / 256, 8, BB), 256, 0, s1>>>(
        pillars, scale, out5, out);

    // s1: final 110 MB needing pos_point
    cudaStreamWaitEvent(s1, ep, 0);
    k_fill_B<<<dim3((HW / 4 + 255) / 256, 2, BB), 256, 0, s1>>>(out4, out);
    cudaEventRecord(e3, s1);

    // join
    cudaStreamWaitEvent(0, e3, 0);
}